// round 5
// baseline (speedup 1.0000x reference)
#include <cuda_runtime.h>
#include <math.h>

typedef unsigned long long ull;

#define BSZ  128
#define NDIM 256
#define HDIM 1024
#define ALPHA 60.0f
#define BETA  20.0f
#define EPSC  1e-8f

// ---- scratch (allocation-free __device__ globals) ----
__device__ __align__(16) float g_p1[3][8][BSZ * HDIM];    // P1 partials
__device__ __align__(16) float g_p2[3][32][BSZ * NDIM];   // P2 partials
__device__ __align__(16) float g_p3[2][8][BSZ * HDIM];    // P3 partials
__device__ __align__(16) float g_p4[2][32][BSZ * NDIM];   // P4 partials
__device__ __align__(16) float g_H [3][BSZ * HDIM];       // tanh hidden
__device__ __align__(16) float g_D [BSZ * HDIM];          // 1 - Hk^2
__device__ __align__(16) float g_fgk[3][BSZ * NDIM];      // f, g, k
__device__ __align__(16) float g_dv[2][BSZ * HDIM];       // (sum p3) * D

__device__ int g_cnt = 0, g_sense = 0;
__device__ int g_ctr[4] = {0, 0, 0, 0};

__device__ __forceinline__ void gbar(int* rst)
{
    __threadfence();
    __syncthreads();
    if (threadIdx.x == 0) {
        int s = *(volatile int*)&g_sense;
        int old = atomicAdd(&g_cnt, 1);
        if (old == (int)gridDim.x - 1) {
            atomicExch(&g_cnt, 0);
            if (rst) atomicExch(rst, 0);
            __threadfence();
            atomicExch(&g_sense, 1 - s);
        } else {
            while (*(volatile int*)&g_sense == s) __nanosleep(64);
        }
        __threadfence();
    }
    __syncthreads();
}

// ---- packed fp32x2 ----
__device__ __forceinline__ ull pk2(float x, float y)
{
    ull r;
    asm("mov.b64 %0, {%1, %2};" : "=l"(r)
        : "r"(__float_as_uint(x)), "r"(__float_as_uint(y)));
    return r;
}
__device__ __forceinline__ void upk2(ull v, float& x, float& y)
{
    unsigned a, b;
    asm("mov.b64 {%0, %1}, %2;" : "=r"(a), "=r"(b) : "l"(v));
    x = __uint_as_float(a);
    y = __uint_as_float(b);
}
#define FMA2(d, a, b) asm("fma.rn.f32x2 %0, %1, %2, %0;" : "+l"(d) : "l"(a), "l"(b))

__device__ __forceinline__ float4 ld4(const float* p)
{
    return *reinterpret_cast<const float4*>(p);
}

// fast-exact tanh: (e-1)/(e+1) form, ex2.approx + rcp.approx, abs err ~1e-7
__device__ __forceinline__ float frcp(float x)
{
    float r;
    asm("rcp.approx.f32 %0, %1;" : "=f"(r) : "f"(x));
    return r;
}
__device__ __forceinline__ float ftanh(float x)
{
    float ax = fabsf(x);
    float e = __expf(ax + ax);
    float t = 1.0f - 2.0f * frcp(e + 1.0f);
    return copysignf(t, x);
}

// ============================================================
// Tile-decode functors: tile id -> (A, B, O) pointers.
// Tiles are 64(M) x 128(N), K-chunk 32.
// ============================================================
struct DecP1 {            // NT: p1[z][s] = x @ W1[z]^T chunk    (T=384)
    const float* x; const float* W[3];
    __device__ __forceinline__ void operator()(int t, const float*& A,
                                               const float*& B, float*& O) const {
        int z = t >> 7, r = t & 127;
        int s = r >> 4, m = (r >> 3) & 1, n = r & 7;
        A = x + m * 64 * NDIM + s * 32;
        B = W[z] + n * 128 * NDIM + s * 32;
        O = g_p1[z][s] + m * 64 * HDIM + n * 128;
    }
};
struct DecP2 {            // NT: p2[z][s] = H[z] @ W2[z]^T chunk (T=384)
    const float* W[3];
    __device__ __forceinline__ void operator()(int t, const float*& A,
                                               const float*& B, float*& O) const {
        int z = t >> 7, r = t & 127;
        int s = r >> 2, m = (r >> 1) & 1, n = r & 1;
        A = g_H[z] + m * 64 * HDIM + s * 32;
        B = W[z] + n * 128 * HDIM + s * 32;
        O = g_p2[z][s] + m * 64 * NDIM + n * 128;
    }
};
struct DecP3 {            // NN: p3[z][s] = fgk[z] @ Wk2 chunk   (T=256)
    const float* Wk2;
    __device__ __forceinline__ void operator()(int t, const float*& A,
                                               const float*& B, float*& O) const {
        int z = t >> 7, r = t & 127;
        int s = r >> 4, m = (r >> 3) & 1, n = r & 7;
        A = g_fgk[z] + m * 64 * NDIM + s * 32;
        B = Wk2 + s * 32 * HDIM + n * 128;
        O = g_p3[z][s] + m * 64 * HDIM + n * 128;
    }
};
struct DecP4 {            // NN: p4[z][s] = dv[z] @ Wk1 chunk    (T=256)
    const float* Wk1;
    __device__ __forceinline__ void operator()(int t, const float*& A,
                                               const float*& B, float*& O) const {
        int z = t >> 7, r = t & 127;
        int s = r >> 2, m = (r >> 1) & 1, n = r & 1;
        A = g_dv[z] + m * 64 * HDIM + s * 32;
        B = Wk1 + s * 32 * NDIM + n * 128;
        O = g_p4[z][s] + m * 64 * NDIM + n * 128;
    }
};

// ============================================================
// GEMM phase driver: work-stealing + cross-tile pipelining.
// Tile 64x128, K=32 (one chunk), 256 threads, m4 x n(4+4) per thread
// via fp32x2 column-pair accumulators.
// BT=true : B is [N,K] K-major (NT).  BT=false: B is [K,N] (NN).
// ============================================================
template <bool BT, class DEC>
__device__ __forceinline__ void gemm_phase(
    int* ctr, int T, int lda, int ldb, int ldo, const DEC& dec,
    float (&As)[32][68], float (&Bs)[32][132], volatile int* s_next)
{
    const int tid = threadIdx.x;
    const int tm = (tid >> 4) * 4;          // 4 output rows
    const int cg = (tid & 15) * 4;          // col quads cg and cg+64
    const int ar = tid >> 2, ak = (tid & 3) * 4;        // A fill
    const int tbr = BT ? (tid >> 1) : (tid >> 3);       // B fill row
    const int tbc = BT ? ((tid & 1) * 16) : ((tid & 7) * 16);

    if (tid == 0) *s_next = atomicAdd(ctr, 1);
    __syncthreads();
    int t = *s_next;

    float4 a0, a1, b0, b1, b2, b3;
    const float *A, *B;
    float *O = nullptr;
    if (t < T) {
        dec(t, A, B, O);
        a0 = ld4(A + ar * lda + ak);
        a1 = ld4(A + ar * lda + ak + 16);
        const float* bp = B + tbr * ldb + tbc;
        b0 = ld4(bp); b1 = ld4(bp + 4); b2 = ld4(bp + 8); b3 = ld4(bp + 12);
    }

    while (t < T) {
        // ---- STS prefetched tile ----
        As[ak + 0][ar] = a0.x; As[ak + 1][ar] = a0.y;
        As[ak + 2][ar] = a0.z; As[ak + 3][ar] = a0.w;
        As[ak + 16][ar] = a1.x; As[ak + 17][ar] = a1.y;
        As[ak + 18][ar] = a1.z; As[ak + 19][ar] = a1.w;
        if (BT) {   // transpose into Bs[k][n]
            Bs[tbc + 0][tbr] = b0.x;  Bs[tbc + 1][tbr] = b0.y;
            Bs[tbc + 2][tbr] = b0.z;  Bs[tbc + 3][tbr] = b0.w;
            Bs[tbc + 4][tbr] = b1.x;  Bs[tbc + 5][tbr] = b1.y;
            Bs[tbc + 6][tbr] = b1.z;  Bs[tbc + 7][tbr] = b1.w;
            Bs[tbc + 8][tbr] = b2.x;  Bs[tbc + 9][tbr] = b2.y;
            Bs[tbc + 10][tbr] = b2.z; Bs[tbc + 11][tbr] = b2.w;
            Bs[tbc + 12][tbr] = b3.x; Bs[tbc + 13][tbr] = b3.y;
            Bs[tbc + 14][tbr] = b3.z; Bs[tbc + 15][tbr] = b3.w;
        } else {    // direct rows
            *reinterpret_cast<float4*>(&Bs[tbr][tbc + 0])  = b0;
            *reinterpret_cast<float4*>(&Bs[tbr][tbc + 4])  = b1;
            *reinterpret_cast<float4*>(&Bs[tbr][tbc + 8])  = b2;
            *reinterpret_cast<float4*>(&Bs[tbr][tbc + 12]) = b3;
        }
        if (tid == 0) *s_next = atomicAdd(ctr, 1);
        __syncthreads();
        const int t2 = *s_next;

        // ---- prefetch next tile into registers (in flight during compute) ----
        float* O2 = nullptr;
        if (t2 < T) {
            const float *A2, *B2;
            dec(t2, A2, B2, O2);
            a0 = ld4(A2 + ar * lda + ak);
            a1 = ld4(A2 + ar * lda + ak + 16);
            const float* bp = B2 + tbr * ldb + tbc;
            b0 = ld4(bp); b1 = ld4(bp + 4); b2 = ld4(bp + 8); b3 = ld4(bp + 12);
        }

        // ---- compute 32 kk from smem ----
        ull acc[4][4];
#pragma unroll
        for (int i = 0; i < 4; i++)
#pragma unroll
            for (int j = 0; j < 4; j++) acc[i][j] = 0ull;

#pragma unroll
        for (int kk = 0; kk < 32; kk++) {
            float4 a = ld4(&As[kk][tm]);
            longlong2 bl = *reinterpret_cast<const longlong2*>(&Bs[kk][cg]);
            longlong2 bh = *reinterpret_cast<const longlong2*>(&Bs[kk][cg + 64]);
            ull bl0 = (ull)bl.x, bl1 = (ull)bl.y;
            ull bh0 = (ull)bh.x, bh1 = (ull)bh.y;
            ull ad0 = pk2(a.x, a.x), ad1 = pk2(a.y, a.y);
            ull ad2 = pk2(a.z, a.z), ad3 = pk2(a.w, a.w);
            FMA2(acc[0][0], ad0, bl0); FMA2(acc[0][1], ad0, bl1);
            FMA2(acc[0][2], ad0, bh0); FMA2(acc[0][3], ad0, bh1);
            FMA2(acc[1][0], ad1, bl0); FMA2(acc[1][1], ad1, bl1);
            FMA2(acc[1][2], ad1, bh0); FMA2(acc[1][3], ad1, bh1);
            FMA2(acc[2][0], ad2, bl0); FMA2(acc[2][1], ad2, bl1);
            FMA2(acc[2][2], ad2, bh0); FMA2(acc[2][3], ad2, bh1);
            FMA2(acc[3][0], ad3, bl0); FMA2(acc[3][1], ad3, bl1);
            FMA2(acc[3][2], ad3, bh0); FMA2(acc[3][3], ad3, bh1);
        }
        __syncthreads();

        // ---- store partial tile ----
#pragma unroll
        for (int i = 0; i < 4; i++) {
            float v0, v1, v2, v3;
            upk2(acc[i][0], v0, v1); upk2(acc[i][1], v2, v3);
            *reinterpret_cast<float4*>(&O[(tm + i) * ldo + cg]) =
                make_float4(v0, v1, v2, v3);
            upk2(acc[i][2], v0, v1); upk2(acc[i][3], v2, v3);
            *reinterpret_cast<float4*>(&O[(tm + i) * ldo + cg + 64]) =
                make_float4(v0, v1, v2, v3);
        }
        t = t2;
        O = O2;
    }
}

// ============================================================
// Persistent fused kernel.
// ============================================================
__global__ __launch_bounds__(256, 2) void fused_kernel(
    const float* __restrict__ x,
    const float* __restrict__ Wf1, const float* __restrict__ bf1,
    const float* __restrict__ Wf2, const float* __restrict__ bf2,
    const float* __restrict__ Wg1, const float* __restrict__ bg1,
    const float* __restrict__ Wg2, const float* __restrict__ bg2,
    const float* __restrict__ Wk1, const float* __restrict__ bk1,
    const float* __restrict__ Wk2, const float* __restrict__ bk2,
    float* __restrict__ out)
{
    __shared__ __align__(16) float As[32][68];
    __shared__ __align__(16) float Bs[32][132];
    __shared__ int s_next;

    const int tid = threadIdx.x;
    const int bid = blockIdx.x;
    const int gstride = gridDim.x * 256;

    // ---- P1: p1 partials (NT) ----
    {
        DecP1 d; d.x = x; d.W[0] = Wf1; d.W[1] = Wg1; d.W[2] = Wk1;
        gemm_phase<true>(&g_ctr[0], 384, NDIM, NDIM, HDIM, d, As, Bs, &s_next);
    }
    gbar(&g_ctr[0]);

    // ---- P1b: H = ftanh(sum8 p1 + b1); D for k ----
    {
        const int PER = BSZ * HDIM / 4;   // 32768 float4 per z
        for (int i4 = bid * 256 + tid; i4 < 3 * PER; i4 += gstride) {
            const int z = i4 / PER;
            const int j = i4 - z * PER;
            const int col4 = j & (HDIM / 4 - 1);
            const float* b1 = (z == 0) ? bf1 : (z == 1) ? bg1 : bk1;
            float4 s = reinterpret_cast<const float4*>(b1)[col4];
#pragma unroll
            for (int p = 0; p < 8; p++) {
                float4 v = reinterpret_cast<const float4*>(g_p1[z][p])[j];
                s.x += v.x; s.y += v.y; s.z += v.z; s.w += v.w;
            }
            float4 h;
            h.x = ftanh(s.x); h.y = ftanh(s.y);
            h.z = ftanh(s.z); h.w = ftanh(s.w);
            reinterpret_cast<float4*>(g_H[z])[j] = h;
            if (z == 2) {
                float4 dd;
                dd.x = 1.0f - h.x * h.x; dd.y = 1.0f - h.y * h.y;
                dd.z = 1.0f - h.z * h.z; dd.w = 1.0f - h.w * h.w;
                reinterpret_cast<float4*>(g_D)[j] = dd;
            }
        }
    }
    gbar(nullptr);

    // ---- P2: p2 partials (NT) ----
    {
        DecP2 d; d.W[0] = Wf2; d.W[1] = Wg2; d.W[2] = Wk2;
        gemm_phase<true>(&g_ctr[1], 384, HDIM, HDIM, NDIM, d, As, Bs, &s_next);
    }
    gbar(&g_ctr[1]);

    // ---- P2b: f,g,k = sum32 p2 + b2 ----
    {
        const int PER = BSZ * NDIM / 4;   // 8192 float4 per z
        for (int i4 = bid * 256 + tid; i4 < 3 * PER; i4 += gstride) {
            const int z = i4 / PER;
            const int j = i4 - z * PER;
            const int col4 = j & (NDIM / 4 - 1);
            const float* b2 = (z == 0) ? bf2 : (z == 1) ? bg2 : bk2;
            float4 s = reinterpret_cast<const float4*>(b2)[col4];
#pragma unroll
            for (int p = 0; p < 32; p++) {
                float4 v = reinterpret_cast<const float4*>(g_p2[z][p])[j];
                s.x += v.x; s.y += v.y; s.z += v.z; s.w += v.w;
            }
            reinterpret_cast<float4*>(g_fgk[z])[j] = s;
        }
    }
    gbar(nullptr);

    // ---- P3: p3 partials (NN) ----
    {
        DecP3 d; d.Wk2 = Wk2;
        gemm_phase<false>(&g_ctr[2], 256, NDIM, HDIM, HDIM, d, As, Bs, &s_next);
    }
    gbar(&g_ctr[2]);

    // ---- P3b: dv = (sum8 p3) * D ----
    {
        const int PER = BSZ * HDIM / 4;
        for (int i4 = bid * 256 + tid; i4 < 2 * PER; i4 += gstride) {
            const int z = i4 / PER;
            const int j = i4 - z * PER;
            float4 s = make_float4(0.f, 0.f, 0.f, 0.f);
#pragma unroll
            for (int p = 0; p < 8; p++) {
                float4 v = reinterpret_cast<const float4*>(g_p3[z][p])[j];
                s.x += v.x; s.y += v.y; s.z += v.z; s.w += v.w;
            }
            float4 dd = reinterpret_cast<const float4*>(g_D)[j];
            s.x *= dd.x; s.y *= dd.y; s.z *= dd.z; s.w *= dd.w;
            reinterpret_cast<float4*>(g_dv[z])[j] = s;
        }
    }
    gbar(nullptr);

    // ---- P4: p4 partials (NN) ----
    {
        DecP4 d; d.Wk1 = Wk1;
        gemm_phase<false>(&g_ctr[3], 256, HDIM, NDIM, NDIM, d, As, Bs, &s_next);
    }
    gbar(&g_ctr[3]);

    // ---- P5: reduce + norms + mask + output ----
    if (bid < BSZ) {
        const int b = bid, i = tid;
        const int idx = b * NDIM + i;

        float jfv = 0.f, jgv = 0.f;
#pragma unroll
        for (int s = 0; s < 32; s++) {
            jfv += g_p4[0][s][idx];
            jgv += g_p4[1][s][idx];
        }
        const float fv = g_fgk[0][idx];
        const float gv = g_fgk[1][idx];
        const float kv = g_fgk[2][idx];

        float kn2 = kv * kv;
        float jf2 = jfv * jfv;
        float dt  = kv * jgv;
#pragma unroll
        for (int off = 16; off > 0; off >>= 1) {
            kn2 += __shfl_down_sync(0xffffffffu, kn2, off);
            jf2 += __shfl_down_sync(0xffffffffu, jf2, off);
            dt  += __shfl_down_sync(0xffffffffu, dt,  off);
        }
        __shared__ float s_kn2[8], s_jf2[8], s_dt[8];
        __shared__ float s_scale;
        const int warp = i >> 5, lane = i & 31;
        if (lane == 0) { s_kn2[warp] = kn2; s_jf2[warp] = jf2; s_dt[warp] = dt; }
        __syncthreads();
        if (i == 0) {
            float tkn2 = 0.f, tjf2 = 0.f, tdt = 0.f;
#pragma unroll
            for (int w = 0; w < 8; w++) {
                tkn2 += s_kn2[w]; tjf2 += s_jf2[w]; tdt += s_dt[w];
            }
            const float kn   = sqrtf(tkn2);
            const float kn9  = tkn2 * tkn2 * tkn2 * tkn2 * kn;
            const float kn10 = kn9 * kn;
            const float c1 = sqrtf(tjf2) - ALPHA * kn9;
            const float c2 = tdt - BETA * kn10;
            const bool mask = (c1 > EPSC) || (c2 < -EPSC);
            s_scale = mask ? 0.5f : 1.0f;
        }
        __syncthreads();
        out[idx] = s_scale * (fv + gv);
    }
}

// inputs: 0:t 1:x 2:Wf1 3:bf1 4:Wf2 5:bf2 6:Wg1 7:bg1 8:Wg2 9:bg2 10:Wk1 11:bk1 12:Wk2 13:bk2
extern "C" void kernel_launch(void* const* d_in, const int* in_sizes, int n_in,
                              void* d_out, int out_size)
{
    const float* x   = (const float*)d_in[1];
    const float* Wf1 = (const float*)d_in[2];
    const float* bf1 = (const float*)d_in[3];
    const float* Wf2 = (const float*)d_in[4];
    const float* bf2 = (const float*)d_in[5];
    const float* Wg1 = (const float*)d_in[6];
    const float* bg1 = (const float*)d_in[7];
    const float* Wg2 = (const float*)d_in[8];
    const float* bg2 = (const float*)d_in[9];
    const float* Wk1 = (const float*)d_in[10];
    const float* bk1 = (const float*)d_in[11];
    const float* Wk2 = (const float*)d_in[12];
    const float* bk2 = (const float*)d_in[13];
    float* out = (float*)d_out;

    int dev = 0;
    cudaGetDevice(&dev);
    int sms = 148;
    cudaDeviceGetAttribute(&sms, cudaDevAttrMultiProcessorCount, dev);
    int occ = 1;
    cudaOccupancyMaxActiveBlocksPerMultiprocessor(&occ, fused_kernel, 256, 0);
    if (occ < 1) occ = 1;
    if (occ > 2) occ = 2;
    int grid = sms * occ;

    fused_kernel<<<grid, 256>>>(x, Wf1, bf1, Wf2, bf2, Wg1, bg1, Wg2, bg2,
                                Wk1, bk1, Wk2, bk2, out);
}